// round 3
// baseline (speedup 1.0000x reference)
#include <cuda_runtime.h>

#define SLICES 32
#define NCH 32            // 8 batches * {img,img_t} * {g,b}
#define NPIX 65536
#define NBIN 256

__device__ float g_hist[NCH][NBIN];   // windowed hist sums (zeroed by reduce_kernel)
__device__ float g_cnt[NCH][NBIN];    // bin counts (zeroed by reduce_kernel)

__device__ __forceinline__ float frcp(float x) {
    float y; asm("rcp.approx.f32 %0, %1;" : "=f"(y) : "f"(x)); return y;
}

// e^{2.5 j} constants
#define E_M1 8.2084998623898800e-02f   // e^-2.5
#define E_P1 12.182493960703473f       // e^2.5
#define E_P2 148.41315910257660f       // e^5

__device__ __forceinline__ void process_pixel(float x, float* s_h, float* s_c) {
    float u = x * 255.0f;
    int k = (int)u;
    if (k > 254) k = 254;
    float f = u - (float)k;
    float e0 = __expf(-2.5f * f);      // e^{-2.5 f}, in [e^-2.5, 1]

    // count: expanded to +1.0 on all thresholds i <= k-2 via suffix-sum in reduce
    atomicAdd(&s_c[k], 1.0f);

    // window j = -1, 0, +1, +2: exact sigmoid via rcp
    if (k >= 1) atomicAdd(&s_h[k - 1], frcp(1.0f + e0 * E_M1));
    atomicAdd(&s_h[k], frcp(1.0f + e0));
    atomicAdd(&s_h[k + 1], frcp(1.0f + e0 * E_P1));   // k+1 <= 255 always
    if (k <= 253) atomicAdd(&s_h[k + 2], frcp(1.0f + e0 * E_P2));
}

__global__ __launch_bounds__(256) void hist_kernel(const float* __restrict__ img,
                                                   const float* __restrict__ img_t) {
    __shared__ float s_h[NBIN];
    __shared__ float s_c[NBIN];
    int t = threadIdx.x;
    s_h[t] = 0.0f;
    s_c[t] = 0.0f;
    __syncthreads();

    int cidx = blockIdx.y;                 // 0..31  (= b*4 + im*2 + ch)
    int slice = blockIdx.x;                // 0..SLICES-1
    int b  = cidx >> 2;
    int im = (cidx >> 1) & 1;
    int ch = cidx & 1;                     // 0 -> g(plane 1), 1 -> b(plane 2)
    const float* src = im ? img_t : img;
    const float4* plane = (const float4*)(src + (size_t)(b * 3 + 1 + ch) * NPIX);

    // 2048 px per slice = 512 float4; 256 threads -> 2 float4 each
    int base = slice * 512;
    #pragma unroll
    for (int v = 0; v < 2; v++) {
        float4 p = plane[base + v * 256 + t];
        process_pixel(p.x, s_h, s_c);
        process_pixel(p.y, s_h, s_c);
        process_pixel(p.z, s_h, s_c);
        process_pixel(p.w, s_h, s_c);
    }
    __syncthreads();

    atomicAdd(&g_hist[cidx][t], s_h[t]);
    atomicAdd(&g_cnt[cidx][t],  s_c[t]);
}

__global__ __launch_bounds__(256) void reduce_kernel(float* __restrict__ out) {
    int b = blockIdx.x;         // batch 0..7
    int t = threadIdx.x;        // 0..255
    __shared__ float sc[4][NBIN];
    __shared__ float H[4][NBIN];
    __shared__ float red[NBIN];

    // channel order: g_img, g_img_t, b_img, b_img_t
    int cid[4] = { b * 4 + 0, b * 4 + 2, b * 4 + 1, b * 4 + 3 };
    #pragma unroll
    for (int q = 0; q < 4; q++) {
        H[q][t]  = g_hist[cid[q]][t];
        sc[q][t] = g_cnt[cid[q]][t];
        // re-zero for the next invocation (module init covers the first call)
        g_hist[cid[q]][t] = 0.0f;
        g_cnt[cid[q]][t]  = 0.0f;
    }
    __syncthreads();

    // inclusive suffix scan of counts
    for (int s = 1; s < NBIN; s <<= 1) {
        float v0 = sc[0][t] + ((t + s < NBIN) ? sc[0][t + s] : 0.0f);
        float v1 = sc[1][t] + ((t + s < NBIN) ? sc[1][t + s] : 0.0f);
        float v2 = sc[2][t] + ((t + s < NBIN) ? sc[2][t + s] : 0.0f);
        float v3 = sc[3][t] + ((t + s < NBIN) ? sc[3][t + s] : 0.0f);
        __syncthreads();
        sc[0][t] = v0; sc[1][t] = v1; sc[2][t] = v2; sc[3][t] = v3;
        __syncthreads();
    }

    // H_total[i] = windowed + (# pixels with bin >= i+2)
    #pragma unroll
    for (int q = 0; q < 4; q++) {
        float suf = (t + 2 < NBIN) ? sc[q][t + 2] : 0.0f;
        H[q][t] = H[q][t] + suf;
    }
    __syncthreads();

    float term = 0.0f;
    if (t < 255) {
        // cdf[J] = (H[0] - H[J+1]) / N ; J = t
        float dg = (H[0][0] - H[0][t + 1]) - (H[1][0] - H[1][t + 1]);
        float db = (H[2][0] - H[2][t + 1]) - (H[3][0] - H[3][t + 1]);
        term = dg * dg + db * db;
    }
    red[t] = term;
    __syncthreads();
    for (int s = 128; s > 0; s >>= 1) {
        if (t < s) red[t] += red[t + s];
        __syncthreads();
    }
    if (t == 0) out[b] = red[0] * (1.0f / (65536.0f * 65536.0f));
}

extern "C" void kernel_launch(void* const* d_in, const int* in_sizes, int n_in,
                              void* d_out, int out_size) {
    const float* img   = (const float*)d_in[0];
    const float* img_t = (const float*)d_in[1];
    float* out = (float*)d_out;

    dim3 grid(SLICES, NCH);
    hist_kernel<<<grid, 256>>>(img, img_t);
    reduce_kernel<<<8, 256>>>(out);
}

// round 4
// speedup vs baseline: 1.3493x; 1.3493x over previous
#include <cuda_runtime.h>

#define SLICES 32
#define NCH 32            // 8 batches * {img,img_t} * {g,b}
#define NPIX 65536
#define NBIN 256

__device__ float g_ph[NCH][SLICES][NBIN];   // per-CTA windowed partials (plain stores)
__device__ float g_pc[NCH][SLICES][NBIN];   // per-CTA count partials
__device__ float g_hist[NCH][NBIN];         // merged
__device__ float g_cnt[NCH][NBIN];          // merged

__device__ __forceinline__ float frcp(float x) {
    float y; asm("rcp.approx.f32 %0, %1;" : "=f"(y) : "f"(x)); return y;
}

// e^{2.5 j} constants
#define E_M1 8.2084998623898800e-02f   // e^-2.5
#define E_P1 12.182493960703473f       // e^2.5
#define E_P2 148.41315910257660f       // e^5

__device__ __forceinline__ void process_pixel(float x, float* s_h, float* s_c) {
    float u = x * 255.0f;
    int k = (int)u;
    if (k > 254) k = 254;
    float f = u - (float)k;
    float e0 = __expf(-2.5f * f);      // e^{-2.5 f}, in [e^-2.5, 1]

    // count: expanded to +1.0 on all thresholds i <= k-2 via suffix-sum later
    atomicAdd(&s_c[k], 1.0f);

    // window j = -1, 0, +1, +2: exact sigmoid via rcp
    if (k >= 1) atomicAdd(&s_h[k - 1], frcp(1.0f + e0 * E_M1));
    atomicAdd(&s_h[k], frcp(1.0f + e0));
    atomicAdd(&s_h[k + 1], frcp(1.0f + e0 * E_P1));   // k+1 <= 255 always
    if (k <= 253) atomicAdd(&s_h[k + 2], frcp(1.0f + e0 * E_P2));
}

__global__ __launch_bounds__(256) void hist_kernel(const float* __restrict__ img,
                                                   const float* __restrict__ img_t) {
    __shared__ float s_h[NBIN];
    __shared__ float s_c[NBIN];
    int t = threadIdx.x;
    s_h[t] = 0.0f;
    s_c[t] = 0.0f;
    __syncthreads();

    int cidx = blockIdx.y;                 // 0..31  (= b*4 + im*2 + ch)
    int slice = blockIdx.x;                // 0..SLICES-1
    int b  = cidx >> 2;
    int im = (cidx >> 1) & 1;
    int ch = cidx & 1;                     // 0 -> g(plane 1), 1 -> b(plane 2)
    const float* src = im ? img_t : img;
    const float4* plane = (const float4*)(src + (size_t)(b * 3 + 1 + ch) * NPIX);

    // 2048 px per slice = 512 float4; 256 threads -> 2 float4 each
    int base = slice * 512;
    #pragma unroll
    for (int v = 0; v < 2; v++) {
        float4 p = plane[base + v * 256 + t];
        process_pixel(p.x, s_h, s_c);
        process_pixel(p.y, s_h, s_c);
        process_pixel(p.z, s_h, s_c);
        process_pixel(p.w, s_h, s_c);
    }
    __syncthreads();

    g_ph[cidx][slice][t] = s_h[t];
    g_pc[cidx][slice][t] = s_c[t];
}

// Merge 32 slices per channel with high MLP (all partials are L2-resident).
__global__ __launch_bounds__(256) void mid_kernel() {
    int c = blockIdx.x;        // channel 0..31
    int t = threadIdx.x;       // bin 0..255
    float h0 = 0.f, h1 = 0.f, c0 = 0.f, c1 = 0.f;
    #pragma unroll
    for (int s = 0; s < SLICES; s += 2) {
        h0 += g_ph[c][s][t];
        h1 += g_ph[c][s + 1][t];
        c0 += g_pc[c][s][t];
        c1 += g_pc[c][s + 1][t];
    }
    g_hist[c][t] = h0 + h1;
    g_cnt[c][t]  = c0 + c1;
}

__global__ __launch_bounds__(256) void final_kernel(float* __restrict__ out) {
    int b = blockIdx.x;         // batch 0..7
    int t = threadIdx.x;        // 0..255
    __shared__ float4 sc4[NBIN];
    __shared__ float H[4][NBIN];
    __shared__ float red[NBIN];

    // channel order: g_img, g_img_t, b_img, b_img_t
    int cid0 = b * 4 + 0, cid1 = b * 4 + 2, cid2 = b * 4 + 1, cid3 = b * 4 + 3;
    H[0][t] = g_hist[cid0][t];
    H[1][t] = g_hist[cid1][t];
    H[2][t] = g_hist[cid2][t];
    H[3][t] = g_hist[cid3][t];
    sc4[t] = make_float4(g_cnt[cid0][t], g_cnt[cid1][t], g_cnt[cid2][t], g_cnt[cid3][t]);
    __syncthreads();

    // inclusive suffix scan of counts (vectorized over the 4 channels)
    for (int s = 1; s < NBIN; s <<= 1) {
        float4 v = sc4[t];
        if (t + s < NBIN) {
            float4 w = sc4[t + s];
            v.x += w.x; v.y += w.y; v.z += w.z; v.w += w.w;
        }
        __syncthreads();
        sc4[t] = v;
        __syncthreads();
    }

    // H_total[i] = windowed + (# pixels with bin >= i+2)
    if (t + 2 < NBIN) {
        float4 suf = sc4[t + 2];
        H[0][t] += suf.x;
        H[1][t] += suf.y;
        H[2][t] += suf.z;
        H[3][t] += suf.w;
    }
    __syncthreads();

    float term = 0.0f;
    if (t < 255) {
        // cdf[J] = (H[0] - H[J+1]) / N ; J = t
        float dg = (H[0][0] - H[0][t + 1]) - (H[1][0] - H[1][t + 1]);
        float db = (H[2][0] - H[2][t + 1]) - (H[3][0] - H[3][t + 1]);
        term = dg * dg + db * db;
    }
    red[t] = term;
    __syncthreads();
    for (int s = 128; s > 0; s >>= 1) {
        if (t < s) red[t] += red[t + s];
        __syncthreads();
    }
    if (t == 0) out[b] = red[0] * (1.0f / (65536.0f * 65536.0f));
}

extern "C" void kernel_launch(void* const* d_in, const int* in_sizes, int n_in,
                              void* d_out, int out_size) {
    const float* img   = (const float*)d_in[0];
    const float* img_t = (const float*)d_in[1];
    float* out = (float*)d_out;

    dim3 grid(SLICES, NCH);
    hist_kernel<<<grid, 256>>>(img, img_t);
    mid_kernel<<<NCH, NBIN>>>();
    final_kernel<<<8, 256>>>(out);
}

// round 5
// speedup vs baseline: 1.5657x; 1.1604x over previous
#include <cuda_runtime.h>

#define SLICES 32
#define NCH 32            // 8 batches * {img,img_t} * {g,b}
#define NPIX 65536
#define NBIN 256

__device__ float g_ph[NCH][SLICES][NBIN];   // per-CTA windowed partials (plain stores)
__device__ float g_pc[NCH][SLICES][NBIN];   // per-CTA count partials
__device__ float g_hist[NCH][NBIN];         // merged
__device__ float g_cnt[NCH][NBIN];          // merged

__device__ __forceinline__ float frcp(float x) {
    float y; asm("rcp.approx.f32 %0, %1;" : "=f"(y) : "f"(x)); return y;
}

// e^{2.5 j} constants
#define E_M1 8.2084998623898800e-02f   // e^-2.5
#define E_P1 12.182493960703473f       // e^2.5

// mean tail values over f~U[0,1):  E_d = 0.4*(ln(1+e^{-2.5(d-1)}) - ln(1+e^{-2.5 d}))
#define ET2 0.0288695f    // mean of sig(2.5(f-2))   (also = mean deficiency at d=-1 side symm)
#define ET3 0.0024650f    // mean of sig(2.5(f-3)) = mean of 1-sig(2.5(f+2))
#define ET4 2.0301e-4f    // mean of sig(2.5(f-4)) = mean of 1-sig(2.5(f+3))

__device__ __forceinline__ void process_pixel(float x, float* s_h1, float* s_c) {
    // s_h1 is the +1-padded hist base (valid indices -1..256 -> 0..257)
    float u = x * 255.0f;
    int k = (int)u;
    if (k > 254) k = 254;
    float f = u - (float)k;
    float e0 = __expf(-2.5f * f);      // e^{-2.5 f}, in [e^-2.5, 1]

    // count marker: expands to +1.0 on thresholds i <= k-2 (suffix-sum) plus tail corrections
    atomicAdd(&s_c[k], 1.0f);

    // exact window d = -1, 0, +1
    atomicAdd(&s_h1[k],     frcp(1.0f + e0 * E_M1));   // threshold k-1
    atomicAdd(&s_h1[k + 1], frcp(1.0f + e0));          // threshold k
    atomicAdd(&s_h1[k + 2], frcp(1.0f + e0 * E_P1));   // threshold k+1
}

__global__ __launch_bounds__(256) void hist_kernel(const float* __restrict__ img,
                                                   const float* __restrict__ img_t) {
    __shared__ float s_h[NBIN + 2];   // padded: index = threshold + 1
    __shared__ float s_c[NBIN];
    int t = threadIdx.x;
    s_h[t] = 0.0f;
    if (t < 2) s_h[NBIN + t] = 0.0f;
    s_c[t] = 0.0f;
    __syncthreads();

    int cidx = blockIdx.y;                 // 0..31  (= b*4 + im*2 + ch)
    int slice = blockIdx.x;                // 0..SLICES-1
    int b  = cidx >> 2;
    int im = (cidx >> 1) & 1;
    int ch = cidx & 1;                     // 0 -> g(plane 1), 1 -> b(plane 2)
    const float* src = im ? img_t : img;
    const float4* plane = (const float4*)(src + (size_t)(b * 3 + 1 + ch) * NPIX);

    // 2048 px per slice = 512 float4; 256 threads -> 2 float4 each
    int base = slice * 512;
    #pragma unroll
    for (int v = 0; v < 2; v++) {
        float4 p = plane[base + v * 256 + t];
        process_pixel(p.x, s_h, s_c);
        process_pixel(p.y, s_h, s_c);
        process_pixel(p.z, s_h, s_c);
        process_pixel(p.w, s_h, s_c);
    }
    __syncthreads();

    g_ph[cidx][slice][t] = s_h[t + 1];   // unpad: threshold t
    g_pc[cidx][slice][t] = s_c[t];
}

// Merge 32 slices per channel with high MLP (all partials are L2-resident).
__global__ __launch_bounds__(256) void mid_kernel() {
    int c = blockIdx.x;        // channel 0..31
    int t = threadIdx.x;       // bin 0..255
    float h0 = 0.f, h1 = 0.f, c0 = 0.f, c1 = 0.f;
    #pragma unroll
    for (int s = 0; s < SLICES; s += 2) {
        h0 += g_ph[c][s][t];
        h1 += g_ph[c][s + 1][t];
        c0 += g_pc[c][s][t];
        c1 += g_pc[c][s + 1][t];
    }
    g_hist[c][t] = h0 + h1;
    g_cnt[c][t]  = c0 + c1;
}

__global__ __launch_bounds__(256) void final_kernel(float* __restrict__ out) {
    int b = blockIdx.x;         // batch 0..7
    int t = threadIdx.x;        // 0..255
    __shared__ float4 rc4[NBIN];   // raw counts (kept for tail corrections)
    __shared__ float4 sc4[NBIN];   // scanned counts
    __shared__ float H[4][NBIN];
    __shared__ float red[NBIN];

    // channel order: g_img, g_img_t, b_img, b_img_t
    int cid0 = b * 4 + 0, cid1 = b * 4 + 2, cid2 = b * 4 + 1, cid3 = b * 4 + 3;
    H[0][t] = g_hist[cid0][t];
    H[1][t] = g_hist[cid1][t];
    H[2][t] = g_hist[cid2][t];
    H[3][t] = g_hist[cid3][t];
    float4 rc = make_float4(g_cnt[cid0][t], g_cnt[cid1][t], g_cnt[cid2][t], g_cnt[cid3][t]);
    rc4[t] = rc;
    sc4[t] = rc;
    __syncthreads();

    // tail mean-compensation: H[i] += ET2*cnt[i-2] + ET3*cnt[i-3] + ET4*cnt[i-4]
    //                                - ET3*cnt[i+2] - ET4*cnt[i+3]
    {
        float4 z = make_float4(0.f, 0.f, 0.f, 0.f);
        float4 m2 = (t >= 2)         ? rc4[t - 2] : z;
        float4 m3 = (t >= 3)         ? rc4[t - 3] : z;
        float4 m4 = (t >= 4)         ? rc4[t - 4] : z;
        float4 p2 = (t + 2 < NBIN)   ? rc4[t + 2] : z;
        float4 p3 = (t + 3 < NBIN)   ? rc4[t + 3] : z;
        H[0][t] += ET2 * m2.x + ET3 * (m3.x - p2.x) + ET4 * (m4.x - p3.x);
        H[1][t] += ET2 * m2.y + ET3 * (m3.y - p2.y) + ET4 * (m4.y - p3.y);
        H[2][t] += ET2 * m2.z + ET3 * (m3.z - p2.z) + ET4 * (m4.z - p3.z);
        H[3][t] += ET2 * m2.w + ET3 * (m3.w - p2.w) + ET4 * (m4.w - p3.w);
    }
    __syncthreads();

    // inclusive suffix scan of counts (vectorized over the 4 channels)
    for (int s = 1; s < NBIN; s <<= 1) {
        float4 v = sc4[t];
        if (t + s < NBIN) {
            float4 w = sc4[t + s];
            v.x += w.x; v.y += w.y; v.z += w.z; v.w += w.w;
        }
        __syncthreads();
        sc4[t] = v;
        __syncthreads();
    }

    // H_total[i] = windowed + corrections + (# pixels with bin >= i+2)
    if (t + 2 < NBIN) {
        float4 suf = sc4[t + 2];
        H[0][t] += suf.x;
        H[1][t] += suf.y;
        H[2][t] += suf.z;
        H[3][t] += suf.w;
    }
    __syncthreads();

    float term = 0.0f;
    if (t < 255) {
        // cdf[J] = (H[0] - H[J+1]) / N ; J = t
        float dg = (H[0][0] - H[0][t + 1]) - (H[1][0] - H[1][t + 1]);
        float db = (H[2][0] - H[2][t + 1]) - (H[3][0] - H[3][t + 1]);
        term = dg * dg + db * db;
    }
    red[t] = term;
    __syncthreads();
    for (int s = 128; s > 0; s >>= 1) {
        if (t < s) red[t] += red[t + s];
        __syncthreads();
    }
    if (t == 0) out[b] = red[0] * (1.0f / (65536.0f * 65536.0f));
}

extern "C" void kernel_launch(void* const* d_in, const int* in_sizes, int n_in,
                              void* d_out, int out_size) {
    const float* img   = (const float*)d_in[0];
    const float* img_t = (const float*)d_in[1];
    float* out = (float*)d_out;

    dim3 grid(SLICES, NCH);
    hist_kernel<<<grid, 256>>>(img, img_t);
    mid_kernel<<<NCH, NBIN>>>();
    final_kernel<<<8, 256>>>(out);
}

// round 6
// speedup vs baseline: 1.7246x; 1.1015x over previous
#include <cuda_runtime.h>

#define SLICES 32
#define NCH 32            // 8 batches * {img,img_t} * {g,b}
#define NPIX 65536
#define NBIN 256

__device__ float g_ph[NCH][SLICES][NBIN];   // per-CTA windowed partials (plain stores)
__device__ float g_pc[NCH][SLICES][NBIN];   // per-CTA encoded count/f-sum partials
__device__ float g_hist[NCH][NBIN];         // merged windowed hist
__device__ float g_cnt[NCH][NBIN];          // merged counts N
__device__ float g_fs[NCH][NBIN];           // merged f-sums S

__device__ __forceinline__ float frcp(float x) {
    float y; asm("rcp.approx.f32 %0, %1;" : "=f"(y) : "f"(x)); return y;
}

#define E_P1 12.182493960703473f       // e^2.5

// linear-fit compensation coefficients: sig(2.5(f-d)) ~= A + B*(f-1/2) over f~U[0,1)
// pairs share B by symmetry: B_d = B_{1-d}
#define A_M1 0.9711630f    // mean of sig(2.5(f+1))      (d=-1)
#define ET2  0.0288370f    // mean of sig(2.5(f-2))      (d=+2)
#define ET3  0.0024650f    // mean of sig(2.5(f-3)); also deficiency at d=-2
#define ET4  0.0002030f    // mean of sig(2.5(f-4)); also deficiency at d=-3
#define B1   0.0639120f    // slope coeff for d=-1 and d=+2
#define B2   0.0056371f    // slope coeff for d=-2 and d=+3
#define B3   0.0004640f    // slope coeff for d=-3 and d=+4

__device__ __forceinline__ void process_pixel(float x, float* s_h1, float* s_c) {
    // s_h1 is the +1-padded hist base: threshold i stored at index i+1
    float u = x * 255.0f;
    int k = (int)u;
    if (k > 254) k = 254;
    float f = u - (float)k;
    float e0 = __expf(-2.5f * f);      // e^{-2.5 f}

    // encoded count: 1024*N + sum(f) recovered in mid_kernel
    atomicAdd(&s_c[k], 1024.0f + f);

    // exact window d = 0, +1
    atomicAdd(&s_h1[k + 1], frcp(1.0f + e0));          // threshold k
    atomicAdd(&s_h1[k + 2], frcp(1.0f + e0 * E_P1));   // threshold k+1
}

__global__ __launch_bounds__(256) void hist_kernel(const float* __restrict__ img,
                                                   const float* __restrict__ img_t) {
    __shared__ float s_h[NBIN + 2];   // padded: index = threshold + 1 (used 1..256)
    __shared__ float s_c[NBIN];
    int t = threadIdx.x;
    s_h[t] = 0.0f;
    if (t < 2) s_h[NBIN + t] = 0.0f;
    s_c[t] = 0.0f;
    __syncthreads();

    int cidx = blockIdx.y;                 // 0..31  (= b*4 + im*2 + ch)
    int slice = blockIdx.x;                // 0..SLICES-1
    int b  = cidx >> 2;
    int im = (cidx >> 1) & 1;
    int ch = cidx & 1;                     // 0 -> g(plane 1), 1 -> b(plane 2)
    const float* src = im ? img_t : img;
    const float4* plane = (const float4*)(src + (size_t)(b * 3 + 1 + ch) * NPIX);

    // 2048 px per slice = 512 float4; 256 threads -> 2 float4 each
    int base = slice * 512;
    #pragma unroll
    for (int v = 0; v < 2; v++) {
        float4 p = plane[base + v * 256 + t];
        process_pixel(p.x, s_h, s_c);
        process_pixel(p.y, s_h, s_c);
        process_pixel(p.z, s_h, s_c);
        process_pixel(p.w, s_h, s_c);
    }
    __syncthreads();

    g_ph[cidx][slice][t] = s_h[t + 1];   // unpad: threshold t
    g_pc[cidx][slice][t] = s_c[t];
}

// Merge 32 slices per channel with high MLP; decode N and S from the encoded sums.
__global__ __launch_bounds__(256) void mid_kernel() {
    int c = blockIdx.x;        // channel 0..31
    int t = threadIdx.x;       // bin 0..255
    float h0 = 0.f, h1 = 0.f, v0 = 0.f, v1 = 0.f;
    #pragma unroll
    for (int s = 0; s < SLICES; s += 2) {
        h0 += g_ph[c][s][t];
        h1 += g_ph[c][s + 1][t];
        v0 += g_pc[c][s][t];
        v1 += g_pc[c][s + 1][t];
    }
    g_hist[c][t] = h0 + h1;
    float v = v0 + v1;                         // 1024*N + S, 0 <= S <= N << 1024
    float N = floorf(v * (1.0f / 1024.0f) + 0.25f);
    g_cnt[c][t] = N;
    g_fs[c][t]  = v - 1024.0f * N;
}

__global__ __launch_bounds__(256) void final_kernel(float* __restrict__ out) {
    int b = blockIdx.x;         // batch 0..7
    int t = threadIdx.x;        // threshold 0..255
    __shared__ float H[4][NBIN];
    __shared__ float4 N4[NBIN];    // counts per bin
    __shared__ float4 D4[NBIN];    // S - N/2 per bin
    __shared__ float4 sc4[NBIN];   // suffix-scanned counts
    __shared__ float red[NBIN];

    // channel order: g_img, g_img_t, b_img, b_img_t
    int cid0 = b * 4 + 0, cid1 = b * 4 + 2, cid2 = b * 4 + 1, cid3 = b * 4 + 3;
    H[0][t] = g_hist[cid0][t];
    H[1][t] = g_hist[cid1][t];
    H[2][t] = g_hist[cid2][t];
    H[3][t] = g_hist[cid3][t];
    float4 n = make_float4(g_cnt[cid0][t], g_cnt[cid1][t], g_cnt[cid2][t], g_cnt[cid3][t]);
    float4 s = make_float4(g_fs[cid0][t],  g_fs[cid1][t],  g_fs[cid2][t],  g_fs[cid3][t]);
    N4[t] = n;
    D4[t] = make_float4(s.x - 0.5f * n.x, s.y - 0.5f * n.y,
                        s.z - 0.5f * n.z, s.w - 0.5f * n.w);
    sc4[t] = n;
    __syncthreads();

    // tail compensation: threshold t gets A*N[k] + B*D[k] from out-of-window bins k
    {
        float ax = 0.f, ay = 0.f, az = 0.f, aw = 0.f;
        #define ACC(IDX, A, B) { int _i = (IDX); if (_i >= 0 && _i < NBIN) { \
            float4 _n = N4[_i]; float4 _d = D4[_i]; \
            ax += (A) * _n.x + (B) * _d.x;  ay += (A) * _n.y + (B) * _d.y; \
            az += (A) * _n.z + (B) * _d.z;  aw += (A) * _n.w + (B) * _d.w; } }
        ACC(t + 1,  A_M1, B1)    // d=-1
        ACC(t - 2,  ET2,  B1)    // d=+2
        ACC(t + 2, -ET3,  B2)    // d=-2 (deficiency vs suffix 1.0)
        ACC(t - 3,  ET3,  B2)    // d=+3
        ACC(t + 3, -ET4,  B3)    // d=-3 (deficiency)
        ACC(t - 4,  ET4,  B3)    // d=+4
        #undef ACC
        H[0][t] += ax; H[1][t] += ay; H[2][t] += az; H[3][t] += aw;
    }
    __syncthreads();

    // inclusive suffix scan of counts (vectorized over the 4 channels)
    for (int st = 1; st < NBIN; st <<= 1) {
        float4 v = sc4[t];
        if (t + st < NBIN) {
            float4 w = sc4[t + st];
            v.x += w.x; v.y += w.y; v.z += w.z; v.w += w.w;
        }
        __syncthreads();
        sc4[t] = v;
        __syncthreads();
    }

    // + (# pixels with bin >= t+2)
    if (t + 2 < NBIN) {
        float4 suf = sc4[t + 2];
        H[0][t] += suf.x;
        H[1][t] += suf.y;
        H[2][t] += suf.z;
        H[3][t] += suf.w;
    }
    __syncthreads();

    float term = 0.0f;
    if (t < 255) {
        // cdf[J] = (H[0] - H[J+1]) / N ; J = t
        float dg = (H[0][0] - H[0][t + 1]) - (H[1][0] - H[1][t + 1]);
        float db = (H[2][0] - H[2][t + 1]) - (H[3][0] - H[3][t + 1]);
        term = dg * dg + db * db;
    }
    red[t] = term;
    __syncthreads();
    for (int st = 128; st > 0; st >>= 1) {
        if (t < st) red[t] += red[t + st];
        __syncthreads();
    }
    if (t == 0) out[b] = red[0] * (1.0f / (65536.0f * 65536.0f));
}

extern "C" void kernel_launch(void* const* d_in, const int* in_sizes, int n_in,
                              void* d_out, int out_size) {
    const float* img   = (const float*)d_in[0];
    const float* img_t = (const float*)d_in[1];
    float* out = (float*)d_out;

    dim3 grid(SLICES, NCH);
    hist_kernel<<<grid, 256>>>(img, img_t);
    mid_kernel<<<NCH, NBIN>>>();
    final_kernel<<<8, 256>>>(out);
}

// round 7
// speedup vs baseline: 2.0701x; 1.2003x over previous
#include <cuda_runtime.h>

#define SLICES 32
#define NCH 32            // 8 batches * {img,img_t} * {g,b}
#define NPIX 65536
#define NBIN 256

__device__ float g_pa[NCH][SLICES][NBIN];   // per-CTA sig0 partials (pure d=0 sums)
__device__ float g_pb[NCH][SLICES][NBIN];   // per-CTA fused 4096*N + sig(+1) partials
__device__ float g_hist[NCH][NBIN];         // merged window hist per threshold
__device__ float g_cnt[NCH][NBIN];          // merged counts N per bin
__device__ float g_D[NCH][NBIN];            // estimated sum(f-1/2) per bin

__device__ __forceinline__ float frcp(float x) {
    float y; asm("rcp.approx.f32 %0, %1;" : "=f"(y) : "f"(x)); return y;
}

#define E_P1 12.182493960703473f       // e^2.5

// sig(2.5f) linear model over f~U[0,1): mean A0, slope b0
#define A0_SIG 0.754354f
#define INV_B0 2.337788f               // 1 / 0.427755

// linear-fit compensation: sig(2.5(f-d)) ~= A + B*(f-1/2);  B_d = B_{1-d}
#define A_M1 0.9711630f    // mean of sig(2.5(f+1))      (d=-1)
#define ET2  0.0288370f    // mean of sig(2.5(f-2))      (d=+2)
#define ET3  0.0024650f    // mean of sig(2.5(f-3)); also deficiency at d=-2
#define ET4  0.0002030f    // mean of sig(2.5(f-4)); also deficiency at d=-3
#define B1   0.0639120f    // slope for d=-1 and d=+2
#define B2   0.0056371f    // slope for d=-2 and d=+3
#define B3   0.0004640f    // slope for d=-3 and d=+4

__device__ __forceinline__ void process_pixel(float x, float* s_a, float* s_b) {
    float u = x * 255.0f;
    int k = (int)u;                    // u < 255 always -> k <= 254, f in [0,1)
    float f = u - (float)k;
    float e0 = __expf(-2.5f * f);      // e^{-2.5 f}

    atomicAdd(&s_a[k], frcp(1.0f + e0));                    // d=0 -> threshold k
    atomicAdd(&s_b[k], 4096.0f + frcp(1.0f + e0 * E_P1));   // count + d=+1 -> threshold k+1
}

__global__ __launch_bounds__(256) void hist_kernel(const float* __restrict__ img,
                                                   const float* __restrict__ img_t) {
    __shared__ float s_a[NBIN];
    __shared__ float s_b[NBIN];
    int t = threadIdx.x;
    s_a[t] = 0.0f;
    s_b[t] = 0.0f;
    __syncthreads();

    int cidx = blockIdx.y;                 // 0..31  (= b*4 + im*2 + ch)
    int slice = blockIdx.x;                // 0..SLICES-1
    int b  = cidx >> 2;
    int im = (cidx >> 1) & 1;
    int ch = cidx & 1;                     // 0 -> g(plane 1), 1 -> b(plane 2)
    const float* src = im ? img_t : img;
    const float4* plane = (const float4*)(src + (size_t)(b * 3 + 1 + ch) * NPIX);

    // 2048 px per slice = 512 float4; 256 threads -> 2 float4 each
    int base = slice * 512;
    #pragma unroll
    for (int v = 0; v < 2; v++) {
        float4 p = plane[base + v * 256 + t];
        process_pixel(p.x, s_a, s_b);
        process_pixel(p.y, s_a, s_b);
        process_pixel(p.z, s_a, s_b);
        process_pixel(p.w, s_a, s_b);
    }
    __syncthreads();

    g_pa[cidx][slice][t] = s_a[t];
    g_pb[cidx][slice][t] = s_b[t];
}

// Merge slices, decode N / window hist / moment estimate.
__global__ __launch_bounds__(256) void mid_kernel() {
    int c = blockIdx.x;        // channel 0..31
    int t = threadIdx.x;       // bin / threshold 0..255
    __shared__ float s_low[NBIN];
    float a0 = 0.f, a1 = 0.f, b0 = 0.f, b1 = 0.f;
    #pragma unroll
    for (int s = 0; s < SLICES; s += 2) {
        a0 += g_pa[c][s][t];
        a1 += g_pa[c][s + 1][t];
        b0 += g_pb[c][s][t];
        b1 += g_pb[c][s + 1][t];
    }
    float a = a0 + a1;
    float bv = b0 + b1;                        // 4096*N + sig(+1)-sum (low < 4096 always)
    float N = floorf(bv * (1.0f / 4096.0f));
    s_low[t] = bv - 4096.0f * N;
    __syncthreads();

    g_hist[c][t] = a + ((t >= 1) ? s_low[t - 1] : 0.0f);
    g_cnt[c][t]  = N;
    g_D[c][t]    = (a - A0_SIG * N) * INV_B0;  // estimated sum(f - 1/2) of bin t
}

__global__ __launch_bounds__(256) void final_kernel(float* __restrict__ out) {
    int b = blockIdx.x;         // batch 0..7
    int t = threadIdx.x;        // threshold 0..255
    __shared__ float H[4][NBIN];
    __shared__ float4 N4[NBIN];    // counts per bin
    __shared__ float4 D4[NBIN];    // estimated sum(f-1/2) per bin
    __shared__ float4 sc4[NBIN];   // suffix-scanned counts
    __shared__ float red[NBIN];

    // channel order: g_img, g_img_t, b_img, b_img_t
    int cid0 = b * 4 + 0, cid1 = b * 4 + 2, cid2 = b * 4 + 1, cid3 = b * 4 + 3;
    H[0][t] = g_hist[cid0][t];
    H[1][t] = g_hist[cid1][t];
    H[2][t] = g_hist[cid2][t];
    H[3][t] = g_hist[cid3][t];
    float4 n = make_float4(g_cnt[cid0][t], g_cnt[cid1][t], g_cnt[cid2][t], g_cnt[cid3][t]);
    N4[t] = n;
    D4[t] = make_float4(g_D[cid0][t], g_D[cid1][t], g_D[cid2][t], g_D[cid3][t]);
    sc4[t] = n;
    __syncthreads();

    // tail compensation: threshold t gets A*N[k] + B*D[k] from out-of-window bins k
    {
        float ax = 0.f, ay = 0.f, az = 0.f, aw = 0.f;
        #define ACC(IDX, A, B) { int _i = (IDX); if (_i >= 0 && _i < NBIN) { \
            float4 _n = N4[_i]; float4 _d = D4[_i]; \
            ax += (A) * _n.x + (B) * _d.x;  ay += (A) * _n.y + (B) * _d.y; \
            az += (A) * _n.z + (B) * _d.z;  aw += (A) * _n.w + (B) * _d.w; } }
        ACC(t + 1,  A_M1, B1)    // d=-1
        ACC(t - 2,  ET2,  B1)    // d=+2
        ACC(t + 2, -ET3,  B2)    // d=-2 (deficiency vs suffix 1.0)
        ACC(t - 3,  ET3,  B2)    // d=+3
        ACC(t + 3, -ET4,  B3)    // d=-3 (deficiency)
        ACC(t - 4,  ET4,  B3)    // d=+4
        #undef ACC
        H[0][t] += ax; H[1][t] += ay; H[2][t] += az; H[3][t] += aw;
    }
    __syncthreads();

    // inclusive suffix scan of counts (vectorized over the 4 channels)
    for (int st = 1; st < NBIN; st <<= 1) {
        float4 v = sc4[t];
        if (t + st < NBIN) {
            float4 w = sc4[t + st];
            v.x += w.x; v.y += w.y; v.z += w.z; v.w += w.w;
        }
        __syncthreads();
        sc4[t] = v;
        __syncthreads();
    }

    // + (# pixels with bin >= t+2)
    if (t + 2 < NBIN) {
        float4 suf = sc4[t + 2];
        H[0][t] += suf.x;
        H[1][t] += suf.y;
        H[2][t] += suf.z;
        H[3][t] += suf.w;
    }
    __syncthreads();

    float term = 0.0f;
    if (t < 255) {
        // cdf[J] = (H[0] - H[J+1]) / N ; J = t
        float dg = (H[0][0] - H[0][t + 1]) - (H[1][0] - H[1][t + 1]);
        float db = (H[2][0] - H[2][t + 1]) - (H[3][0] - H[3][t + 1]);
        term = dg * dg + db * db;
    }
    red[t] = term;
    __syncthreads();
    for (int st = 128; st > 0; st >>= 1) {
        if (t < st) red[t] += red[t + st];
        __syncthreads();
    }
    if (t == 0) out[b] = red[0] * (1.0f / (65536.0f * 65536.0f));
}

extern "C" void kernel_launch(void* const* d_in, const int* in_sizes, int n_in,
                              void* d_out, int out_size) {
    const float* img   = (const float*)d_in[0];
    const float* img_t = (const float*)d_in[1];
    float* out = (float*)d_out;

    dim3 grid(SLICES, NCH);
    hist_kernel<<<grid, 256>>>(img, img_t);
    mid_kernel<<<NCH, NBIN>>>();
    final_kernel<<<8, 256>>>(out);
}